// round 16
// baseline (speedup 1.0000x reference)
#include <cuda_runtime.h>
#include <cstdint>

// GestureRNN: 2-layer ReLU RNN, B=4096, T=512, IN=10, H=32, NCLS=9.
// R16 = R14's 128-register body (verified correct, regs==128) run at
// block=128 so warps land on ALL FOUR SMSPs (R14's block=64 put every
// warp on SMSP 0/1 — that, not the diet, caused its 544us), with
// __launch_bounds__(128,4) -> 16 warps/SM (4/SMSP, was 3/SMSP at R12's
// 168 regs). Plus one prefetch.global.L1 of the next x-group issued a
// full step ahead of its reload (fixes R14's exposed L2 latency).
//  - single 80B x-group buffer (20 regs): even-step seeds from odd half,
//    reload <- G(g+1) between the paired steps, odd-step seeds from the
//    reloaded even half.
//  - layer-1 chains merged (wi1+wh1 share aA/aB).
//  - 1 syncwarp/step, parity double-buffered h1/h2, register-carried w0
//    partial + xp seeds (R12/R14 structure).

typedef unsigned long long ull;

__device__ __forceinline__ ull ffma2(ull a, ull b, ull c) {
    ull d;
    asm("fma.rn.f32x2 %0, %1, %2, %3;" : "=l"(d) : "l"(a), "l"(b), "l"(c));
    return d;
}
__device__ __forceinline__ ull fadd2(ull a, ull b) {
    ull d;
    asm("add.rn.f32x2 %0, %1, %2;" : "=l"(d) : "l"(a), "l"(b));
    return d;
}
__device__ __forceinline__ float hsum2(ull a) {
    return __uint_as_float((unsigned)a) + __uint_as_float((unsigned)(a >> 32));
}

static constexpr int T_STEPS = 512;
static constexpr int BATCH   = 4096;
static constexpr int IN_DIM  = 10;
static constexpr int NCLS    = 9;
static constexpr int WARPS   = 4;   // 128-thread CTAs: warps on all 4 SMSPs

struct __align__(16) WarpBuf {
    float h1[2][32];
    float h2[2][32];
};

__global__ void __launch_bounds__(WARPS * 32, 4) rnn_fused_kernel(
    const float* __restrict__ x,
    const float* __restrict__ Wih0, const float* __restrict__ Whh0,
    const float* __restrict__ bih0, const float* __restrict__ bhh0,
    const float* __restrict__ Wih1, const float* __restrict__ Whh1,
    const float* __restrict__ bih1, const float* __restrict__ bhh1,
    const float* __restrict__ Wfc,  const float* __restrict__ bfc,
    float* __restrict__ out)
{
    __shared__ WarpBuf buf[WARPS];

    const int w   = threadIdx.x >> 5;
    const int lid = threadIdx.x & 31;
    const int b   = blockIdx.x * WARPS + w;
    WarpBuf& wb = buf[w];

    // ---- per-lane weight rows, packed f32x2 over k-pairs ----
    ull w0[16], wi1[16], wh1[16], xw[5];
    {
        const ulonglong2* p0 = (const ulonglong2*)(Whh0 + lid * 32);
        const ulonglong2* p1 = (const ulonglong2*)(Wih1 + lid * 32);
        const ulonglong2* p2 = (const ulonglong2*)(Whh1 + lid * 32);
#pragma unroll
        for (int m = 0; m < 8; m++) {
            ulonglong2 a = p0[m]; w0[2*m]  = a.x; w0[2*m+1]  = a.y;
            ulonglong2 c = p1[m]; wi1[2*m] = c.x; wi1[2*m+1] = c.y;
            ulonglong2 d = p2[m]; wh1[2*m] = d.x; wh1[2*m+1] = d.y;
        }
        const ull* px = (const ull*)(Wih0 + lid * IN_DIM);  // 40B rows, 8B aligned
#pragma unroll
        for (int m = 0; m < 5; m++) xw[m] = px[m];
    }
    const float b0f = bih0[lid] + bhh0[lid];
    const float b1f = bih1[lid] + bhh1[lid];

    wb.h2[0][lid] = 0.f;

    // x groups: group g = steps 2g,2g+1 = 80B = 5 x ulonglong2, 16B aligned
    // (batch base 20480B, group stride 80B).
    const ulonglong2* xgp = (const ulonglong2*)(x + (size_t)b * (T_STEPS * IN_DIM));

    ulonglong2 xG[5];
#pragma unroll
    for (int j = 0; j < 5; j++) xG[j] = xgp[j];   // G(0)

    // carry seed for step 0: xw . x_0 (even half of G(0));  h1_{-1} = 0
    ull carA, carB;
    carA = ffma2(xw[0], xG[0].x, (ull)0);
    carB = ffma2(xw[1], xG[0].y, (ull)0);
    carA = ffma2(xw[2], xG[1].x, carA);
    carB = ffma2(xw[3], xG[1].y, carB);
    carA = ffma2(xw[4], xG[2].x, carA);

    // One recurrence step. P = parity (t&1), seeds s0..s4 = packed pairs of
    // x_{t+1} feeding the carry-chain init. Layer-1 uses ONE merged chain
    // pair (aA,aB) across wi1 and wh1.
#define RNN_STEP(P, s0, s1, s2, s3, s4)                                       \
    {                                                                         \
        const int Q = (P) ^ 1;                                                \
        float h1n = fmaxf(b0f + hsum2(fadd2(carA, carB)), 0.f);               \
        wb.h1[(P)][lid] = h1n;                                                \
        __syncwarp();                                                         \
        ull nA = ffma2(xw[0], (s0), (ull)0);                                  \
        ull nB = ffma2(xw[1], (s1), (ull)0);                                  \
        nA = ffma2(xw[2], (s2), nA);                                          \
        nB = ffma2(xw[3], (s3), nB);                                          \
        nA = ffma2(xw[4], (s4), nA);                                          \
        const ulonglong2* h1p = (const ulonglong2*)wb.h1[(P)];                \
        const ulonglong2* h2p = (const ulonglong2*)wb.h2[(P)];                \
        ull aA = 0ull, aB = 0ull;                                             \
        _Pragma("unroll")                                                     \
        for (int m = 0; m < 8; m++) {                                         \
            ulonglong2 qa = h1p[m];                                           \
            aA = ffma2(wi1[2*m],   qa.x, aA);                                 \
            aB = ffma2(wi1[2*m+1], qa.y, aB);                                 \
            nA = ffma2(w0[2*m],    qa.x, nA);                                 \
            nB = ffma2(w0[2*m+1],  qa.y, nB);                                 \
        }                                                                     \
        _Pragma("unroll")                                                     \
        for (int m = 0; m < 8; m++) {                                         \
            ulonglong2 ra = h2p[m];                                           \
            aA = ffma2(wh1[2*m],   ra.x, aA);                                 \
            aB = ffma2(wh1[2*m+1], ra.y, aB);                                 \
        }                                                                     \
        float h2n = fmaxf(b1f + hsum2(fadd2(aA, aB)), 0.f);                   \
        wb.h2[Q][lid] = h2n;                                                  \
        carA = nA; carB = nB;                                                 \
    }

    for (int g = 0; g < T_STEPS / 2; g++) {
        // prefetch G(g+1) a full step before its reload (hint: never faults,
        // no registers; covers L2/DRAM latency for the reload below)
        asm volatile("prefetch.global.L1 [%0];" :: "l"(xgp + 5 * (g + 1)));

        // step 2g (P=0): seed x_{2g+1} = odd half of G(g)
        RNN_STEP(0, xG[2].y, xG[3].x, xG[3].y, xG[4].x, xG[4].y);

        // reload xG <- G(g+1) (clamped; garbage only seeds the dead final carry)
        {
            const int gn = (g + 1 < T_STEPS / 2) ? (g + 1) : (T_STEPS / 2 - 1);
            const ulonglong2* src = xgp + 5 * gn;
#pragma unroll
            for (int j = 0; j < 5; j++) xG[j] = src[j];
        }

        // step 2g+1 (P=1): seed x_{2g+2} = even half of G(g+1)
        RNN_STEP(1, xG[0].x, xG[0].y, xG[1].x, xG[1].y, xG[2].x);
    }
#undef RNN_STEP
    __syncwarp();

    // classifier head: t=511 (P=1) wrote h2 parity 0
    if (lid < NCLS) {
        float o = bfc[lid];
        const float* wr  = Wfc + lid * 32;
        const float* h2f = wb.h2[0];
#pragma unroll
        for (int j = 0; j < 32; j++) o += h2f[j] * wr[j];
        out[(size_t)b * NCLS + lid] = o;
    }
}

extern "C" void kernel_launch(void* const* d_in, const int* in_sizes, int n_in,
                              void* d_out, int out_size)
{
    const float* x    = (const float*)d_in[0];
    const float* Wih0 = (const float*)d_in[1];
    const float* Whh0 = (const float*)d_in[2];
    const float* bih0 = (const float*)d_in[3];
    const float* bhh0 = (const float*)d_in[4];
    const float* Wih1 = (const float*)d_in[5];
    const float* Whh1 = (const float*)d_in[6];
    const float* bih1 = (const float*)d_in[7];
    const float* bhh1 = (const float*)d_in[8];
    const float* Wfc  = (const float*)d_in[9];
    const float* bfc  = (const float*)d_in[10];
    float* out = (float*)d_out;

    rnn_fused_kernel<<<BATCH / WARPS, WARPS * 32>>>(
        x, Wih0, Whh0, bih0, bhh0, Wih1, Whh1, bih1, bhh1, Wfc, bfc, out);
}

// round 17
// speedup vs baseline: 1.2779x; 1.2779x over previous
#include <cuda_runtime.h>
#include <cstdint>

// GestureRNN: 2-layer ReLU RNN, B=4096, T=512, IN=10, H=32, NCLS=9.
// R17 = R12 (409us, session best) + ONE delta: layer-1 accumulator chains
// merged (wi1+wh1 share aA/aB; -2 fadd2 in the h2 epilogue, -4 regs).
// Everything else byte-identical to R12: block=128, lb(128,3), dual x
// group buffers at 2-group prefetch distance (keeps L2% at ~1.6 - the
// single-buffer variants R14/R16 exposed 8-14% L2 latency), 4-step
// unroll, 1 syncwarp/step, parity double-buffered h1/h2, register-
// carried w0 partial with xp seeds replacing the carry-chain zero-init.

typedef unsigned long long ull;

__device__ __forceinline__ ull ffma2(ull a, ull b, ull c) {
    ull d;
    asm("fma.rn.f32x2 %0, %1, %2, %3;" : "=l"(d) : "l"(a), "l"(b), "l"(c));
    return d;
}
__device__ __forceinline__ ull fadd2(ull a, ull b) {
    ull d;
    asm("add.rn.f32x2 %0, %1, %2;" : "=l"(d) : "l"(a), "l"(b));
    return d;
}
__device__ __forceinline__ float hsum2(ull a) {
    return __uint_as_float((unsigned)a) + __uint_as_float((unsigned)(a >> 32));
}

static constexpr int T_STEPS = 512;
static constexpr int BATCH   = 4096;
static constexpr int IN_DIM  = 10;
static constexpr int NCLS    = 9;
static constexpr int WARPS   = 4;   // 128-thread CTAs

struct __align__(16) WarpBuf {
    float h1[2][32];
    float h2[2][32];
};

__global__ void __launch_bounds__(WARPS * 32, 3) rnn_fused_kernel(
    const float* __restrict__ x,
    const float* __restrict__ Wih0, const float* __restrict__ Whh0,
    const float* __restrict__ bih0, const float* __restrict__ bhh0,
    const float* __restrict__ Wih1, const float* __restrict__ Whh1,
    const float* __restrict__ bih1, const float* __restrict__ bhh1,
    const float* __restrict__ Wfc,  const float* __restrict__ bfc,
    float* __restrict__ out)
{
    __shared__ WarpBuf buf[WARPS];

    const int w   = threadIdx.x >> 5;
    const int lid = threadIdx.x & 31;
    const int b   = blockIdx.x * WARPS + w;
    WarpBuf& wb = buf[w];

    // ---- per-lane weight rows, packed f32x2 over k-pairs ----
    ull w0[16], wi1[16], wh1[16], xw[5];
    {
        const ulonglong2* p0 = (const ulonglong2*)(Whh0 + lid * 32);
        const ulonglong2* p1 = (const ulonglong2*)(Wih1 + lid * 32);
        const ulonglong2* p2 = (const ulonglong2*)(Whh1 + lid * 32);
#pragma unroll
        for (int m = 0; m < 8; m++) {
            ulonglong2 a = p0[m]; w0[2*m]  = a.x; w0[2*m+1]  = a.y;
            ulonglong2 c = p1[m]; wi1[2*m] = c.x; wi1[2*m+1] = c.y;
            ulonglong2 d = p2[m]; wh1[2*m] = d.x; wh1[2*m+1] = d.y;
        }
        const ull* px = (const ull*)(Wih0 + lid * IN_DIM);  // 40B rows, 8B aligned
#pragma unroll
        for (int m = 0; m < 5; m++) xw[m] = px[m];
    }
    const float b0f = bih0[lid] + bhh0[lid];
    const float b1f = bih1[lid] + bhh1[lid];

    wb.h2[0][lid] = 0.f;

    // x groups: group g = steps 2g,2g+1 = 80B = 5 x ulonglong2 (16B aligned:
    // batch base is 20480B, group stride 80B).
    const ulonglong2* xgp = (const ulonglong2*)(x + (size_t)b * (T_STEPS * IN_DIM));

    ulonglong2 xA[5], xB[5];
#pragma unroll
    for (int j = 0; j < 5; j++) { xA[j] = xgp[j]; xB[j] = xgp[5 + j]; }

    // carry seed for step 0: xw . x_0 (even pairs of group 0)
    ull carA, carB;
    carA = ffma2(xw[0], xA[0].x, (ull)0);
    carB = ffma2(xw[1], xA[0].y, (ull)0);
    carA = ffma2(xw[2], xA[1].x, carA);
    carB = ffma2(xw[3], xA[1].y, carB);
    carA = ffma2(xw[4], xA[2].x, carA);

    // One recurrence step. P = parity (t&1), seeds s0..s4 = packed pairs of
    // x_{t+1} feeding the carry-chain init. Layer-1 uses ONE merged chain
    // pair (aA,aB) across wi1 and wh1 (the sole delta vs R12).
#define RNN_STEP(P, s0, s1, s2, s3, s4)                                       \
    {                                                                         \
        const int Q = (P) ^ 1;                                                \
        float h1n = fmaxf(b0f + hsum2(fadd2(carA, carB)), 0.f);               \
        wb.h1[(P)][lid] = h1n;                                                \
        __syncwarp();                                                         \
        const ulonglong2* h1p = (const ulonglong2*)wb.h1[(P)];                \
        const ulonglong2* h2p = (const ulonglong2*)wb.h2[(P)];                \
        ull aA = 0ull, aB = 0ull;                                             \
        ull nA = ffma2(xw[0], (s0), (ull)0);                                  \
        ull nB = ffma2(xw[1], (s1), (ull)0);                                  \
        nA = ffma2(xw[2], (s2), nA);                                          \
        nB = ffma2(xw[3], (s3), nB);                                          \
        nA = ffma2(xw[4], (s4), nA);                                          \
        _Pragma("unroll")                                                     \
        for (int m = 0; m < 8; m++) {                                         \
            ulonglong2 qa = h1p[m];                                           \
            ulonglong2 ra = h2p[m];                                           \
            aA = ffma2(wi1[2*m],   qa.x, aA);                                 \
            aB = ffma2(wi1[2*m+1], qa.y, aB);                                 \
            nA = ffma2(w0[2*m],    qa.x, nA);                                 \
            nB = ffma2(w0[2*m+1],  qa.y, nB);                                 \
            aA = ffma2(wh1[2*m],   ra.x, aA);                                 \
            aB = ffma2(wh1[2*m+1], ra.y, aB);                                 \
        }                                                                     \
        float h2n = fmaxf(b1f + hsum2(fadd2(aA, aB)), 0.f);                   \
        wb.h2[Q][lid] = h2n;                                                  \
        carA = nA; carB = nB;                                                 \
    }

    for (int t4 = 0; t4 < T_STEPS; t4 += 4) {
        const int g = t4 >> 1;           // xA = G(g), xB = G(g+1)

        // step t4 (P=0): seed x_{t4+1} = odd of G(g)
        RNN_STEP(0, xA[2].y, xA[3].x, xA[3].y, xA[4].x, xA[4].y);

        // reload xA <- G(g+2) (clamped; garbage only seeds the dead final carry)
        {
            const int gn = (g + 2 < T_STEPS / 2) ? (g + 2) : (T_STEPS / 2 - 1);
            const ulonglong2* src = xgp + 5 * gn;
#pragma unroll
            for (int j = 0; j < 5; j++) xA[j] = src[j];
        }

        // step t4+1 (P=1): seed x_{t4+2} = even of G(g+1)
        RNN_STEP(1, xB[0].x, xB[0].y, xB[1].x, xB[1].y, xB[2].x);

        // step t4+2 (P=0): seed x_{t4+3} = odd of G(g+1)
        RNN_STEP(0, xB[2].y, xB[3].x, xB[3].y, xB[4].x, xB[4].y);

        // reload xB <- G(g+3) (clamped)
        {
            const int gn = (g + 3 < T_STEPS / 2) ? (g + 3) : (T_STEPS / 2 - 1);
            const ulonglong2* src = xgp + 5 * gn;
#pragma unroll
            for (int j = 0; j < 5; j++) xB[j] = src[j];
        }

        // step t4+3 (P=1): seed x_{t4+4} = even of G(g+2) (reloaded xA)
        RNN_STEP(1, xA[0].x, xA[0].y, xA[1].x, xA[1].y, xA[2].x);
    }
#undef RNN_STEP
    __syncwarp();

    // classifier head: t=511 (P=1) wrote h2 parity 0
    if (lid < NCLS) {
        float o = bfc[lid];
        const float* wr  = Wfc + lid * 32;
        const float* h2f = wb.h2[0];
#pragma unroll
        for (int j = 0; j < 32; j++) o += h2f[j] * wr[j];
        out[(size_t)b * NCLS + lid] = o;
    }
}

extern "C" void kernel_launch(void* const* d_in, const int* in_sizes, int n_in,
                              void* d_out, int out_size)
{
    const float* x    = (const float*)d_in[0];
    const float* Wih0 = (const float*)d_in[1];
    const float* Whh0 = (const float*)d_in[2];
    const float* bih0 = (const float*)d_in[3];
    const float* bhh0 = (const float*)d_in[4];
    const float* Wih1 = (const float*)d_in[5];
    const float* Whh1 = (const float*)d_in[6];
    const float* bih1 = (const float*)d_in[7];
    const float* bhh1 = (const float*)d_in[8];
    const float* Wfc  = (const float*)d_in[9];
    const float* bfc  = (const float*)d_in[10];
    float* out = (float*)d_out;

    rnn_fused_kernel<<<BATCH / WARPS, WARPS * 32>>>(
        x, Wih0, Whh0, bih0, bhh0, Wih1, Whh1, bih1, bhh1, Wfc, bfc, out);
}